// round 13
// baseline (speedup 1.0000x reference)
#include <cuda_runtime.h>
#include <cuda_fp16.h>
#include <math_constants.h>
#include <cstdint>

// ============================================================================
// scores = h_P @ volP^T + h ; per-column (over p) max/argmax ; bincount/8192.
// 2-way fp16 split, 3 cross products in ONE fp16 GEMM via K-concatenation:
//   A' (volP): [ah(100) | ah(100) | al(100) | 0(20)]   K = 320
//   B' (h_P) : [bh(100) | bl(100) | bh(100) | 0(20)]
// A-STATIONARY + WARP-DECOUPLED, warp tile 64n x 64p; per-warp private
// 3-stage cp.async B pipeline; no __syncthreads in main loop.
// R13: full-step fragment staging (16 LDSM up front -> 64-MMA burst),
//      fused prep kernel (expand A + expand B + zero g in one launch).
// ============================================================================

#define NUM_P   16384
#define BATN    8192
#define DIM     100
#define KEXP    320
#define KSTEPS  10                  // 32-K steps per p-tile
#define PCHUNKS 16
#define PCH     (NUM_P / PCHUNKS)   // 1024
#define NT      64                  // n rows per block
#define TP      256                 // p rows per tile (64 per warp)
#define PTILES  (PCH / TP)          // 4
#define TOT     (PTILES * KSTEPS)   // 40
#define THREADS 128

// smem layout (bytes):
//   A resident: 64 rows x 656B   = 41984
//   B stages  : 3 x (256 x 80B)  = 61440   at ABOFF
//   reduce    : 2048             at REDOFF
#define AROW_B      656
#define BROW_B      80
#define ABOFF       41984
#define BSTAGE_B    20480
#define REDOFF      (ABOFF + 3 * BSTAGE_B)   // 103424
#define SMEM_TOTAL  (REDOFF + 2048)          // 105472

// ---------------- device scratch ----------------
__device__ __half g_A[(size_t)BATN  * KEXP];   // 5.2 MB
__device__ __half g_B[(size_t)NUM_P * KEXP];   // 10.5 MB
__device__ float g_pv[PCHUNKS * BATN];
__device__ int   g_pi[PCHUNKS * BATN];

// ---------------- asm helpers ----------------
__device__ __forceinline__ uint32_t smem_u32(const void* p) {
    uint32_t a;
    asm("{ .reg .u64 t; cvta.to.shared.u64 t, %1; cvt.u32.u64 %0, t; }" : "=r"(a) : "l"(p));
    return a;
}
__device__ __forceinline__ void cp16(uint32_t saddr, const void* gptr) {
    asm volatile("cp.async.cg.shared.global [%0], [%1], 16;"
                 :: "r"(saddr), "l"(__cvta_generic_to_global((void*)gptr)) : "memory");
}
#define CP_COMMIT() asm volatile("cp.async.commit_group;" ::: "memory")
#define CP_WAIT(n)  asm volatile("cp.async.wait_group %0;" :: "n"(n) : "memory")

#define LDSM4(r, addr) \
    asm volatile("ldmatrix.sync.aligned.m8n8.x4.shared.b16 {%0,%1,%2,%3}, [%4];" \
        : "=r"((r)[0]), "=r"((r)[1]), "=r"((r)[2]), "=r"((r)[3]) : "r"(addr))

#define MMA16816(c, a, b0, b1) \
    asm volatile("mma.sync.aligned.m16n8k16.row.col.f32.f16.f16.f32 " \
        "{%0,%1,%2,%3},{%4,%5,%6,%7},{%8,%9},{%0,%1,%2,%3};" \
        : "+f"((c)[0]), "+f"((c)[1]), "+f"((c)[2]), "+f"((c)[3]) \
        : "r"((a)[0]), "r"((a)[1]), "r"((a)[2]), "r"((a)[3]), "r"(b0), "r"(b1))

// ---------------- prep: expand A rows, expand B rows, zero g (one launch) ---
__global__ void prep_kernel(const float* __restrict__ X,
                            const float* __restrict__ P,
                            float* __restrict__ gout) {
    const int b = blockIdx.x;
    const int k = threadIdx.x * 2;            // 0,2,..,318
    const int isB = (b >= BATN);
    const int row = isB ? (b - BATN) : b;
    const float* src = isB ? P : X;
    __half* dst = isB ? g_B : g_A;

    if (!isB && threadIdx.x < 2)              // A blocks: zero g (2 per block)
        gout[2 * b + threadIdx.x] = 0.0f;

    __half2 o = __floats2half2_rn(0.0f, 0.0f);
    const int blk = (k < 100) ? 0 : (k < 200) ? 1 : (k < 300) ? 2 : 3;
    if (blk < 3) {
        const int kk = k - blk * 100;
        float2 v = *reinterpret_cast<const float2*>(src + (size_t)row * DIM + kk);
        __half h0 = __float2half_rn(v.x), h1 = __float2half_rn(v.y);
        bool want_lo = isB ? (blk == 1) : (blk == 2);
        if (want_lo) {
            o = __halves2half2(__float2half_rn(v.x - __half2float(h0)),
                               __float2half_rn(v.y - __half2float(h1)));
        } else {
            o = __halves2half2(h0, h1);
        }
    }
    *reinterpret_cast<__half2*>(dst + (size_t)row * KEXP + k) = o;
}

// ---------------- main fused GEMM + argmax ----------------
__global__ __launch_bounds__(THREADS, 2)
void ot_mma_kernel(const float* __restrict__ h) {
    extern __shared__ char smem[];
    const uint32_t smb = smem_u32(smem);
    const int tid = threadIdx.x;
    const int L   = tid & 31;
    const int wp  = tid >> 5;          // 0..3 : p-dim slice (64 cols each)
    const int nt  = blockIdx.x >> 4;   // 0..127
    const int pc  = blockIdx.x & 15;   // 0..15
    const int nbase  = nt * NT;
    const int pchunk = pc * PCH;

    // ldmatrix lane geometry
    const int mat = L >> 3, l8 = L & 7;
    const int arow = ((mat & 1) << 3) + l8, akh = (mat >> 1) << 3;
    const int brow = ((mat >> 1) << 3) + l8, bkh = (mat & 1) << 3;
    uint32_t aoffs[4], boffb[4];
#pragma unroll
    for (int mi = 0; mi < 4; mi++)       // A resident, absolute smem address
        aoffs[mi] = smb + (uint32_t)((mi * 16 + arow) * AROW_B + akh * 2);
#pragma unroll
    for (int g = 0; g < 4; g++)          // B stage-relative: row stride 80B
        boffb[g] = (uint32_t)((wp * 64 + g * 16 + brow) * BROW_B + bkh * 2);

    // per-warp B loader: warp wp owns B rows [wp*64, wp*64+64) of each tile.
    // lane L -> rows wp*64 + (L>>2) + 8i (i=0..7), 16B chunk (L&3).
    const int brow0 = wp * 64 + (L >> 2);
    const uint32_t dBw = (uint32_t)(brow0 * BROW_B + (L & 3) * 16);
    const __half* bBw = g_B + (size_t)(pchunk + brow0) * KEXP + (L & 3) * 8;

#define LOAD_BSTAGE(stageaddr, srcB_, ksB) do {                                  \
    const uint32_t _st = (stageaddr);                                            \
    _Pragma("unroll")                                                            \
    for (int _i = 0; _i < 8; _i++)                                               \
        cp16(_st + dBw + (uint32_t)_i * 8 * BROW_B,                              \
             (srcB_) + (size_t)_i * 8 * KEXP + (ksB) * 32);                      \
} while (0)

    // ---- prologue
    // G0: A resident (2560 x 16B, all threads)
    {
        const __half* Ab = g_A + (size_t)nbase * KEXP;
#pragma unroll
        for (int i = 0; i < 20; i++) {
            int q = tid + i * THREADS;          // 0..2559
            int row = q / 40, c = q - row * 40;
            cp16(smb + (uint32_t)(row * AROW_B + c * 16),
                 Ab + (size_t)row * KEXP + c * 8);
        }
        CP_COMMIT();
    }
    // G1: B stage 0 ; G2: B stage 1  (per-warp slices)
    LOAD_BSTAGE(smb + ABOFF, bBw, 0);
    CP_COMMIT();
    LOAD_BSTAGE(smb + ABOFF + BSTAGE_B, bBw, 1);
    CP_COMMIT();
    CP_WAIT(2);            // G0 (this thread's A chunks) landed
    __syncthreads();       // ALL threads' A chunks landed -> A readable by all

    float acc[4][8][4];
#pragma unroll
    for (int mi = 0; mi < 4; mi++)
#pragma unroll
        for (int pi = 0; pi < 8; pi++)
#pragma unroll
            for (int q = 0; q < 4; q++) acc[mi][pi][q] = 0.0f;

    float bv[4][2];
    int   bi[4][2];
#pragma unroll
    for (int mi = 0; mi < 4; mi++)
#pragma unroll
        for (int hf = 0; hf < 2; hf++) { bv[mi][hf] = -CUDART_INF_F; bi[mi][hf] = 0; }

    int ks = 0, p0 = pchunk;           // current tile state
    int pfk = 2;                       // prefetch k-step within its tile
    const __half* pBw = bBw;           // prefetch-tile B base (per warp)

    for (int gs = 0; gs < TOT; gs++) {
        CP_WAIT(1);        // this warp's stage gs landed (1 group/step/thread)
        __syncwarp();      // publish lanes' cp.async bytes across the warp

        // prefetch this warp's B slice for step gs+2 (rolls across tiles)
        if (gs + 2 < TOT) {
            LOAD_BSTAGE(smb + ABOFF + (uint32_t)((gs + 2) % 3) * BSTAGE_B, pBw, pfk);
        }
        CP_COMMIT();       // exactly one group per step keeps wait-count math
        if (++pfk == KSTEPS) { pfk = 0; pBw += (size_t)TP * KEXP; }

        // ---- full-step fragment staging: issue ALL 16 LDSM, then 64 MMAs.
        const uint32_t sbB = smb + ABOFF + (uint32_t)(gs % 3) * BSTAGE_B;
        const uint32_t ak  = (uint32_t)(ks * 64);
        uint32_t af[2][4][4], bf[2][4][4];
#pragma unroll
        for (int kh = 0; kh < 2; kh++) {
            const uint32_t ko = (uint32_t)kh * 32;
#pragma unroll
            for (int mi = 0; mi < 4; mi++) LDSM4(af[kh][mi], aoffs[mi] + ak + ko);
#pragma unroll
            for (int g = 0; g < 4; g++)    LDSM4(bf[kh][g], sbB + boffb[g] + ko);
        }
#pragma unroll
        for (int kh = 0; kh < 2; kh++)
#pragma unroll
            for (int mi = 0; mi < 4; mi++)
#pragma unroll
                for (int pi = 0; pi < 8; pi++) {
                    const int g = pi >> 1, q = (pi & 1) * 2;
                    MMA16816(acc[mi][pi], af[kh][mi], bf[kh][g][q], bf[kh][g][q + 1]);
                }

        // end of p-tile: fold accumulators (register-only)
        if (ks == KSTEPS - 1) {
#pragma unroll
            for (int pi = 0; pi < 8; pi++) {
                const int pA = p0 + wp * 64 + pi * 8 + (L & 3) * 2;
                const float h0 = __ldg(h + pA), h1 = __ldg(h + pA + 1);
#pragma unroll
                for (int mi = 0; mi < 4; mi++)
#pragma unroll
                    for (int hf = 0; hf < 2; hf++) {
                        float s0 = acc[mi][pi][hf * 2 + 0] + h0;
                        float s1 = acc[mi][pi][hf * 2 + 1] + h1;
                        if (s0 > bv[mi][hf]) { bv[mi][hf] = s0; bi[mi][hf] = pA; }
                        if (s1 > bv[mi][hf]) { bv[mi][hf] = s1; bi[mi][hf] = pA + 1; }
                        acc[mi][pi][hf * 2 + 0] = 0.0f;
                        acc[mi][pi][hf * 2 + 1] = 0.0f;
                    }
            }
            ks = 0; p0 += TP;
        } else {
            ks++;
        }
    }

    // reduce: lanes sharing an n-row differ in L&3 (disjoint p); then across
    // the 4 warps (disjoint p slices, wp ascending = p ascending).
    __syncthreads();
    float* rv = reinterpret_cast<float*>(smem + REDOFF);          // [4][64]
    int*   ri = reinterpret_cast<int*>(smem + REDOFF + 1024);     // [4][64]
#pragma unroll
    for (int mi = 0; mi < 4; mi++)
#pragma unroll
        for (int hf = 0; hf < 2; hf++) {
            float v = bv[mi][hf];
            int   i = bi[mi][hf];
#pragma unroll
            for (int off = 1; off <= 2; off <<= 1) {
                float ov = __shfl_xor_sync(0xffffffffu, v, off);
                int   oi = __shfl_xor_sync(0xffffffffu, i, off);
                if (ov > v || (ov == v && oi < i)) { v = ov; i = oi; }
            }
            if ((L & 3) == 0) {
                int row = mi * 16 + (L >> 2) + hf * 8;            // 0..63
                rv[wp * 64 + row] = v;
                ri[wp * 64 + row] = i;
            }
        }
    __syncthreads();
    if (tid < NT) {
        float v = rv[tid]; int i = ri[tid];
#pragma unroll
        for (int w = 1; w < 4; w++) {
            float ov = rv[w * 64 + tid]; int oi = ri[w * 64 + tid];
            if (ov > v) { v = ov; i = oi; }
        }
        g_pv[pc * BATN + nbase + tid] = v;
        g_pi[pc * BATN + nbase + tid] = i;
    }
}

// ---------------- combine chunks + outputs + bincount ----------------
__global__ void combine_kernel(float* __restrict__ out) {
    int n = blockIdx.x * blockDim.x + threadIdx.x;
    if (n >= BATN) return;
    float v = g_pv[n]; int i = g_pi[n];
#pragma unroll
    for (int c = 1; c < PCHUNKS; c++) {
        float cv = g_pv[c * BATN + n]; int ci = g_pi[c * BATN + n];
        if (cv > v) { v = cv; i = ci; }       // chunks ascending in p
    }
    out[n]        = v;
    out[BATN + n] = (float)i;
    atomicAdd(&out[2 * BATN + i], 1.0f / (float)BATN);
}

// ---------------- launch ----------------
extern "C" void kernel_launch(void* const* d_in, const int* in_sizes, int n_in,
                              void* d_out, int out_size) {
    const float* P = (const float*)d_in[0];   // h_P [16384,100]
    const float* h = (const float*)d_in[1];   // h   [16384]
    const float* X = (const float*)d_in[2];   // volP[8192,100]
    float* out = (float*)d_out;
    (void)in_sizes; (void)n_in; (void)out_size;

    static bool attr_set = false;
    if (!attr_set) {
        cudaFuncSetAttribute(ot_mma_kernel,
                             cudaFuncAttributeMaxDynamicSharedMemorySize, SMEM_TOTAL);
        attr_set = true;
    }

    prep_kernel<<<BATN + NUM_P, KEXP / 2>>>(X, P, out + 2 * BATN);
    ot_mma_kernel<<<128 * PCHUNKS, THREADS, SMEM_TOTAL>>>(h);
    combine_kernel<<<(BATN + 255) / 256, 256>>>(out);
}

// round 14
// speedup vs baseline: 1.0698x; 1.0698x over previous
#include <cuda_runtime.h>
#include <cuda_fp16.h>
#include <math_constants.h>
#include <cstdint>

// ============================================================================
// scores = h_P @ volP^T + h ; per-column (over p) max/argmax ; bincount/8192.
// 2-way fp16 split, 3 cross products in ONE fp16 GEMM via K-concatenation:
//   A' (volP): [ah(100) | ah(100) | al(100) | 0(20)]   K = 320
//   B' (h_P) : [bh(100) | bl(100) | bh(100) | 0(20)]
// A-STATIONARY + WARP-DECOUPLED, warp tile 64n x 64p; per-warp private
// 3-stage cp.async B pipeline; no __syncthreads in main loop.
// R14: R12 per-half LDSM/MMA order (R13 staging reverted) + fused prep +
//      fully unrolled k-step loop (compile-time ks/ak/prefetch offsets).
// ============================================================================

#define NUM_P   16384
#define BATN    8192
#define DIM     100
#define KEXP    320
#define KSTEPS  10                  // 32-K steps per p-tile
#define PCHUNKS 16
#define PCH     (NUM_P / PCHUNKS)   // 1024
#define NT      64                  // n rows per block
#define TP      256                 // p rows per tile (64 per warp)
#define PTILES  (PCH / TP)          // 4
#define THREADS 128

// smem layout (bytes):
//   A resident: 64 rows x 656B   = 41984
//   B stages  : 3 x (256 x 80B)  = 61440   at ABOFF
//   reduce    : 2048             at REDOFF
#define AROW_B      656
#define BROW_B      80
#define ABOFF       41984
#define BSTAGE_B    20480
#define REDOFF      (ABOFF + 3 * BSTAGE_B)   // 103424
#define SMEM_TOTAL  (REDOFF + 2048)          // 105472

// ---------------- device scratch ----------------
__device__ __half g_A[(size_t)BATN  * KEXP];   // 5.2 MB
__device__ __half g_B[(size_t)NUM_P * KEXP];   // 10.5 MB
__device__ float g_pv[PCHUNKS * BATN];
__device__ int   g_pi[PCHUNKS * BATN];

// ---------------- asm helpers ----------------
__device__ __forceinline__ uint32_t smem_u32(const void* p) {
    uint32_t a;
    asm("{ .reg .u64 t; cvta.to.shared.u64 t, %1; cvt.u32.u64 %0, t; }" : "=r"(a) : "l"(p));
    return a;
}
__device__ __forceinline__ void cp16(uint32_t saddr, const void* gptr) {
    asm volatile("cp.async.cg.shared.global [%0], [%1], 16;"
                 :: "r"(saddr), "l"(__cvta_generic_to_global((void*)gptr)) : "memory");
}
#define CP_COMMIT() asm volatile("cp.async.commit_group;" ::: "memory")
#define CP_WAIT(n)  asm volatile("cp.async.wait_group %0;" :: "n"(n) : "memory")

#define LDSM4(r, addr) \
    asm volatile("ldmatrix.sync.aligned.m8n8.x4.shared.b16 {%0,%1,%2,%3}, [%4];" \
        : "=r"((r)[0]), "=r"((r)[1]), "=r"((r)[2]), "=r"((r)[3]) : "r"(addr))

#define MMA16816(c, a, b0, b1) \
    asm volatile("mma.sync.aligned.m16n8k16.row.col.f32.f16.f16.f32 " \
        "{%0,%1,%2,%3},{%4,%5,%6,%7},{%8,%9},{%0,%1,%2,%3};" \
        : "+f"((c)[0]), "+f"((c)[1]), "+f"((c)[2]), "+f"((c)[3]) \
        : "r"((a)[0]), "r"((a)[1]), "r"((a)[2]), "r"((a)[3]), "r"(b0), "r"(b1))

// ---------------- prep: expand A rows, expand B rows, zero g (one launch) ---
__global__ void prep_kernel(const float* __restrict__ X,
                            const float* __restrict__ P,
                            float* __restrict__ gout) {
    const int b = blockIdx.x;
    const int k = threadIdx.x * 2;            // 0,2,..,318
    const int isB = (b >= BATN);
    const int row = isB ? (b - BATN) : b;
    const float* src = isB ? P : X;
    __half* dst = isB ? g_B : g_A;

    if (!isB && threadIdx.x < 2)              // A blocks: zero g (2 per block)
        gout[2 * b + threadIdx.x] = 0.0f;

    __half2 o = __floats2half2_rn(0.0f, 0.0f);
    const int blk = (k < 100) ? 0 : (k < 200) ? 1 : (k < 300) ? 2 : 3;
    if (blk < 3) {
        const int kk = k - blk * 100;
        float2 v = *reinterpret_cast<const float2*>(src + (size_t)row * DIM + kk);
        __half h0 = __float2half_rn(v.x), h1 = __float2half_rn(v.y);
        bool want_lo = isB ? (blk == 1) : (blk == 2);
        if (want_lo) {
            o = __halves2half2(__float2half_rn(v.x - __half2float(h0)),
                               __float2half_rn(v.y - __half2float(h1)));
        } else {
            o = __halves2half2(h0, h1);
        }
    }
    *reinterpret_cast<__half2*>(dst + (size_t)row * KEXP + k) = o;
}

// ---------------- main fused GEMM + argmax ----------------
__global__ __launch_bounds__(THREADS, 2)
void ot_mma_kernel(const float* __restrict__ h) {
    extern __shared__ char smem[];
    const uint32_t smb = smem_u32(smem);
    const int tid = threadIdx.x;
    const int L   = tid & 31;
    const int wp  = tid >> 5;          // 0..3 : p-dim slice (64 cols each)
    const int nt  = blockIdx.x >> 4;   // 0..127
    const int pc  = blockIdx.x & 15;   // 0..15
    const int nbase  = nt * NT;
    const int pchunk = pc * PCH;

    // ldmatrix lane geometry
    const int mat = L >> 3, l8 = L & 7;
    const int arow = ((mat & 1) << 3) + l8, akh = (mat >> 1) << 3;
    const int brow = ((mat >> 1) << 3) + l8, bkh = (mat & 1) << 3;
    uint32_t aoffs[4], boffb[4];
#pragma unroll
    for (int mi = 0; mi < 4; mi++)       // A resident, absolute smem address
        aoffs[mi] = smb + (uint32_t)((mi * 16 + arow) * AROW_B + akh * 2);
#pragma unroll
    for (int g = 0; g < 4; g++)          // B stage-relative: row stride 80B
        boffb[g] = (uint32_t)((wp * 64 + g * 16 + brow) * BROW_B + bkh * 2);

    // per-warp B loader: warp wp owns B rows [wp*64, wp*64+64) of each tile.
    // lane L -> rows wp*64 + (L>>2) + 8i (i=0..7), 16B chunk (L&3).
    const int brow0 = wp * 64 + (L >> 2);
    const uint32_t dBw = (uint32_t)(brow0 * BROW_B + (L & 3) * 16);
    const __half* bBw = g_B + (size_t)(pchunk + brow0) * KEXP + (L & 3) * 8;

// src pointer already carries the k-step offset
#define LOAD_BSTAGE(stageaddr, srcB_) do {                                       \
    const uint32_t _st = (stageaddr);                                            \
    _Pragma("unroll")                                                            \
    for (int _i = 0; _i < 8; _i++)                                               \
        cp16(_st + dBw + (uint32_t)_i * 8 * BROW_B,                              \
             (srcB_) + (size_t)_i * 8 * KEXP);                                   \
} while (0)

    // ---- prologue
    // G0: A resident (2560 x 16B, all threads)
    {
        const __half* Ab = g_A + (size_t)nbase * KEXP;
#pragma unroll
        for (int i = 0; i < 20; i++) {
            int q = tid + i * THREADS;          // 0..2559
            int row = q / 40, c = q - row * 40;
            cp16(smb + (uint32_t)(row * AROW_B + c * 16),
                 Ab + (size_t)row * KEXP + c * 8);
        }
        CP_COMMIT();
    }
    // G1: B stage 0 ; G2: B stage 1  (per-warp slices, tile 0, ks 0/1)
    LOAD_BSTAGE(smb + ABOFF, bBw);
    CP_COMMIT();
    LOAD_BSTAGE(smb + ABOFF + BSTAGE_B, bBw + 32);
    CP_COMMIT();
    CP_WAIT(2);            // G0 (this thread's A chunks) landed
    __syncthreads();       // ALL threads' A chunks landed -> A readable by all

    float acc[4][8][4];
#pragma unroll
    for (int mi = 0; mi < 4; mi++)
#pragma unroll
        for (int pi = 0; pi < 8; pi++)
#pragma unroll
            for (int q = 0; q < 4; q++) acc[mi][pi][q] = 0.0f;

    float bv[4][2];
    int   bi[4][2];
#pragma unroll
    for (int mi = 0; mi < 4; mi++)
#pragma unroll
        for (int hf = 0; hf < 2; hf++) { bv[mi][hf] = -CUDART_INF_F; bi[mi][hf] = 0; }

    // 3-stage ring offsets (dynamic; TOT=40 not divisible by 3)
    uint32_t csOff = 0;                    // compute stage byte offset
    uint32_t pfOff = 2 * BSTAGE_B;         // prefetch stage byte offset
    const __half* pBt = bBw;               // current tile's B base (per warp)

    for (int pt = 0; pt < PTILES; pt++) {
#pragma unroll
        for (int ks = 0; ks < KSTEPS; ks++) {
            CP_WAIT(1);    // this warp's stage landed (1 group/step/thread)
            __syncwarp();  // publish lanes' cp.async bytes across the warp

            // prefetch this warp's B slice 2 steps ahead (compile-time ks)
            const int ks2 = ks + 2;
            if (ks2 < KSTEPS) {
                LOAD_BSTAGE(smb + ABOFF + pfOff, pBt + ks2 * 32);
            } else if (pt < PTILES - 1) {
                LOAD_BSTAGE(smb + ABOFF + pfOff,
                            pBt + (size_t)TP * KEXP + (ks2 - KSTEPS) * 32);
            }
            CP_COMMIT();   // exactly one group per step keeps wait-count math

            // compute: A resident (K offset ks*64B const), B from stage
            const uint32_t sbB = smb + ABOFF + csOff;
#pragma unroll
            for (int kh = 0; kh < 2; kh++) {
                const uint32_t ko = (uint32_t)(ks * 64 + kh * 32);
                uint32_t af[4][4], bf[4][4];
#pragma unroll
                for (int mi = 0; mi < 4; mi++) LDSM4(af[mi], aoffs[mi] + ko);
#pragma unroll
                for (int g = 0; g < 4; g++)
                    LDSM4(bf[g], sbB + boffb[g] + (uint32_t)(kh * 32));
#pragma unroll
                for (int mi = 0; mi < 4; mi++)
#pragma unroll
                    for (int pi = 0; pi < 8; pi++) {
                        const int g = pi >> 1, q = (pi & 1) * 2;
                        MMA16816(acc[mi][pi], af[mi], bf[g][q], bf[g][q + 1]);
                    }
            }

            // advance ring offsets (2 ALU each)
            csOff += BSTAGE_B; if (csOff == 3 * BSTAGE_B) csOff = 0;
            pfOff += BSTAGE_B; if (pfOff == 3 * BSTAGE_B) pfOff = 0;
        }

        // end of p-tile: fold accumulators (register-only)
        const int p0 = pchunk + pt * TP;
#pragma unroll
        for (int pi = 0; pi < 8; pi++) {
            const int pA = p0 + wp * 64 + pi * 8 + (L & 3) * 2;
            const float h0 = __ldg(h + pA), h1 = __ldg(h + pA + 1);
#pragma unroll
            for (int mi = 0; mi < 4; mi++)
#pragma unroll
                for (int hf = 0; hf < 2; hf++) {
                    float s0 = acc[mi][pi][hf * 2 + 0] + h0;
                    float s1 = acc[mi][pi][hf * 2 + 1] + h1;
                    if (s0 > bv[mi][hf]) { bv[mi][hf] = s0; bi[mi][hf] = pA; }
                    if (s1 > bv[mi][hf]) { bv[mi][hf] = s1; bi[mi][hf] = pA + 1; }
                    acc[mi][pi][hf * 2 + 0] = 0.0f;
                    acc[mi][pi][hf * 2 + 1] = 0.0f;
                }
        }
        pBt += (size_t)TP * KEXP;
    }

    // reduce: lanes sharing an n-row differ in L&3 (disjoint p); then across
    // the 4 warps (disjoint p slices, wp ascending = p ascending).
    __syncthreads();
    float* rv = reinterpret_cast<float*>(smem + REDOFF);          // [4][64]
    int*   ri = reinterpret_cast<int*>(smem + REDOFF + 1024);     // [4][64]
#pragma unroll
    for (int mi = 0; mi < 4; mi++)
#pragma unroll
        for (int hf = 0; hf < 2; hf++) {
            float v = bv[mi][hf];
            int   i = bi[mi][hf];
#pragma unroll
            for (int off = 1; off <= 2; off <<= 1) {
                float ov = __shfl_xor_sync(0xffffffffu, v, off);
                int   oi = __shfl_xor_sync(0xffffffffu, i, off);
                if (ov > v || (ov == v && oi < i)) { v = ov; i = oi; }
            }
            if ((L & 3) == 0) {
                int row = mi * 16 + (L >> 2) + hf * 8;            // 0..63
                rv[wp * 64 + row] = v;
                ri[wp * 64 + row] = i;
            }
        }
    __syncthreads();
    if (tid < NT) {
        float v = rv[tid]; int i = ri[tid];
#pragma unroll
        for (int w = 1; w < 4; w++) {
            float ov = rv[w * 64 + tid]; int oi = ri[w * 64 + tid];
            if (ov > v) { v = ov; i = oi; }
        }
        g_pv[pc * BATN + nbase + tid] = v;
        g_pi[pc * BATN + nbase + tid] = i;
    }
}

// ---------------- combine chunks + outputs + bincount ----------------
__global__ void combine_kernel(float* __restrict__ out) {
    int n = blockIdx.x * blockDim.x + threadIdx.x;
    if (n >= BATN) return;
    float v = g_pv[n]; int i = g_pi[n];
#pragma unroll
    for (int c = 1; c < PCHUNKS; c++) {
        float cv = g_pv[c * BATN + n]; int ci = g_pi[c * BATN + n];
        if (cv > v) { v = cv; i = ci; }       // chunks ascending in p
    }
    out[n]        = v;
    out[BATN + n] = (float)i;
    atomicAdd(&out[2 * BATN + i], 1.0f / (float)BATN);
}

// ---------------- launch ----------------
extern "C" void kernel_launch(void* const* d_in, const int* in_sizes, int n_in,
                              void* d_out, int out_size) {
    const float* P = (const float*)d_in[0];   // h_P [16384,100]
    const float* h = (const float*)d_in[1];   // h   [16384]
    const float* X = (const float*)d_in[2];   // volP[8192,100]
    float* out = (float*)d_out;
    (void)in_sizes; (void)n_in; (void)out_size;

    static bool attr_set = false;
    if (!attr_set) {
        cudaFuncSetAttribute(ot_mma_kernel,
                             cudaFuncAttributeMaxDynamicSharedMemorySize, SMEM_TOTAL);
        attr_set = true;
    }

    prep_kernel<<<BATN + NUM_P, KEXP / 2>>>(X, P, out + 2 * BATN);
    ot_mma_kernel<<<128 * PCHUNKS, THREADS, SMEM_TOTAL>>>(h);
    combine_kernel<<<(BATN + 255) / 256, 256>>>(out);
}

// round 16
// speedup vs baseline: 1.1332x; 1.0593x over previous
#include <cuda_runtime.h>
#include <cuda_fp16.h>
#include <math_constants.h>
#include <cstdint>

// ============================================================================
// scores = h_P @ volP^T + h ; per-column (over p) max/argmax ; bincount/8192.
// 2-way fp16 split, 3 cross products in ONE fp16 GEMM via K-concatenation:
//   A' (volP): [ah(100) | ah(100) | al(100) | 0(20)]   K = 320
//   B' (h_P) : [bh(100) | bl(100) | bh(100) | 0(20)]
// A-STATIONARY + WARP-DECOUPLED, warp tile 64n x 64p; per-warp private
// 3-stage cp.async B pipeline; no __syncthreads in main loop; unrolled ks.
// R15/16: skip all-pad half-step (ks=9,kh=1 covers K[304,320) = zeros) and
//         vectorized prep (16B stores, 8 halves/thread, fused g-zeroing).
// ============================================================================

#define NUM_P   16384
#define BATN    8192
#define DIM     100
#define KEXP    320
#define KSTEPS  10                  // 32-K steps per p-tile
#define PCHUNKS 16
#define PCH     (NUM_P / PCHUNKS)   // 1024
#define NT      64                  // n rows per block
#define TP      256                 // p rows per tile (64 per warp)
#define PTILES  (PCH / TP)          // 4
#define THREADS 128

// smem layout (bytes):
//   A resident: 64 rows x 656B   = 41984
//   B stages  : 3 x (256 x 80B)  = 61440   at ABOFF
//   reduce    : 2048             at REDOFF
#define AROW_B      656
#define BROW_B      80
#define ABOFF       41984
#define BSTAGE_B    20480
#define REDOFF      (ABOFF + 3 * BSTAGE_B)   // 103424
#define SMEM_TOTAL  (REDOFF + 2048)          // 105472

// ---------------- device scratch ----------------
__device__ __half g_A[(size_t)BATN  * KEXP];   // 5.2 MB
__device__ __half g_B[(size_t)NUM_P * KEXP];   // 10.5 MB
__device__ float g_pv[PCHUNKS * BATN];
__device__ int   g_pi[PCHUNKS * BATN];

// ---------------- asm helpers ----------------
__device__ __forceinline__ uint32_t smem_u32(const void* p) {
    uint32_t a;
    asm("{ .reg .u64 t; cvta.to.shared.u64 t, %1; cvt.u32.u64 %0, t; }" : "=r"(a) : "l"(p));
    return a;
}
__device__ __forceinline__ void cp16(uint32_t saddr, const void* gptr) {
    asm volatile("cp.async.cg.shared.global [%0], [%1], 16;"
                 :: "r"(saddr), "l"(__cvta_generic_to_global((void*)gptr)) : "memory");
}
#define CP_COMMIT() asm volatile("cp.async.commit_group;" ::: "memory")
#define CP_WAIT(n)  asm volatile("cp.async.wait_group %0;" :: "n"(n) : "memory")

#define LDSM4(r, addr) \
    asm volatile("ldmatrix.sync.aligned.m8n8.x4.shared.b16 {%0,%1,%2,%3}, [%4];" \
        : "=r"((r)[0]), "=r"((r)[1]), "=r"((r)[2]), "=r"((r)[3]) : "r"(addr))

#define MMA16816(c, a, b0, b1) \
    asm volatile("mma.sync.aligned.m16n8k16.row.col.f32.f16.f16.f32 " \
        "{%0,%1,%2,%3},{%4,%5,%6,%7},{%8,%9},{%0,%1,%2,%3};" \
        : "+f"((c)[0]), "+f"((c)[1]), "+f"((c)[2]), "+f"((c)[3]) \
        : "r"((a)[0]), "r"((a)[1]), "r"((a)[2]), "r"((a)[3]), "r"(b0), "r"(b1))

// ---------------- prep: 8 halves/thread, one 16B store; fused g-zero --------
// chunk id g covers dst[row][c*8 .. c*8+8) with row = g/40, c = g%40.
__global__ __launch_bounds__(256)
void prep_kernel(const float* __restrict__ X,
                 const float* __restrict__ P,
                 float* __restrict__ gout) {
    const int g = blockIdx.x * 256 + threadIdx.x;     // 0 .. 983039
    if (g >= (BATN + NUM_P) * 40) return;
    if (g < NUM_P) gout[g] = 0.0f;                    // zero g region
    const int row = g / 40;
    const int c   = g - row * 40;
    const int isB = (row >= BATN);
    const int r   = isB ? (row - BATN) : row;
    const float* src = (isB ? P : X) + (size_t)r * DIM;

    __half o[8];
#pragma unroll
    for (int j = 0; j < 8; j++) {
        const int k = c * 8 + j;
        const int blk = (k < 100) ? 0 : (k < 200) ? 1 : (k < 300) ? 2 : 3;
        if (blk == 3) { o[j] = __float2half_rn(0.0f); continue; }
        const float x = src[k - blk * 100];
        const __half hi = __float2half_rn(x);
        const bool want_lo = isB ? (blk == 1) : (blk == 2);
        o[j] = want_lo ? __float2half_rn(x - __half2float(hi)) : hi;
    }
    __half* dst = (isB ? g_B : g_A) + (size_t)r * KEXP + c * 8;
    *reinterpret_cast<int4*>(dst) = *reinterpret_cast<const int4*>(o);
}

// ---------------- main fused GEMM + argmax ----------------
__global__ __launch_bounds__(THREADS, 2)
void ot_mma_kernel(const float* __restrict__ h) {
    extern __shared__ char smem[];
    const uint32_t smb = smem_u32(smem);
    const int tid = threadIdx.x;
    const int L   = tid & 31;
    const int wp  = tid >> 5;          // 0..3 : p-dim slice (64 cols each)
    const int nt  = blockIdx.x >> 4;   // 0..127
    const int pc  = blockIdx.x & 15;   // 0..15
    const int nbase  = nt * NT;
    const int pchunk = pc * PCH;

    // ldmatrix lane geometry
    const int mat = L >> 3, l8 = L & 7;
    const int arow = ((mat & 1) << 3) + l8, akh = (mat >> 1) << 3;
    const int brow = ((mat >> 1) << 3) + l8, bkh = (mat & 1) << 3;
    uint32_t aoffs[4], boffb[4];
#pragma unroll
    for (int mi = 0; mi < 4; mi++)       // A resident, absolute smem address
        aoffs[mi] = smb + (uint32_t)((mi * 16 + arow) * AROW_B + akh * 2);
#pragma unroll
    for (int g = 0; g < 4; g++)          // B stage-relative: row stride 80B
        boffb[g] = (uint32_t)((wp * 64 + g * 16 + brow) * BROW_B + bkh * 2);

    // per-warp B loader: warp wp owns B rows [wp*64, wp*64+64) of each tile.
    // lane L -> rows wp*64 + (L>>2) + 8i (i=0..7), 16B chunk (L&3).
    const int brow0 = wp * 64 + (L >> 2);
    const uint32_t dBw = (uint32_t)(brow0 * BROW_B + (L & 3) * 16);
    const __half* bBw = g_B + (size_t)(pchunk + brow0) * KEXP + (L & 3) * 8;

// src pointer already carries the k-step offset
#define LOAD_BSTAGE(stageaddr, srcB_) do {                                       \
    const uint32_t _st = (stageaddr);                                            \
    _Pragma("unroll")                                                            \
    for (int _i = 0; _i < 8; _i++)                                               \
        cp16(_st + dBw + (uint32_t)_i * 8 * BROW_B,                              \
             (srcB_) + (size_t)_i * 8 * KEXP);                                   \
} while (0)

    // ---- prologue
    // G0: A resident (2560 x 16B, all threads)
    {
        const __half* Ab = g_A + (size_t)nbase * KEXP;
#pragma unroll
        for (int i = 0; i < 20; i++) {
            int q = tid + i * THREADS;          // 0..2559
            int row = q / 40, c = q - row * 40;
            cp16(smb + (uint32_t)(row * AROW_B + c * 16),
                 Ab + (size_t)row * KEXP + c * 8);
        }
        CP_COMMIT();
    }
    // G1: B stage 0 ; G2: B stage 1  (per-warp slices, tile 0, ks 0/1)
    LOAD_BSTAGE(smb + ABOFF, bBw);
    CP_COMMIT();
    LOAD_BSTAGE(smb + ABOFF + BSTAGE_B, bBw + 32);
    CP_COMMIT();
    CP_WAIT(2);            // G0 (this thread's A chunks) landed
    __syncthreads();       // ALL threads' A chunks landed -> A readable by all

    float acc[4][8][4];
#pragma unroll
    for (int mi = 0; mi < 4; mi++)
#pragma unroll
        for (int pi = 0; pi < 8; pi++)
#pragma unroll
            for (int q = 0; q < 4; q++) acc[mi][pi][q] = 0.0f;

    float bv[4][2];
    int   bi[4][2];
#pragma unroll
    for (int mi = 0; mi < 4; mi++)
#pragma unroll
        for (int hf = 0; hf < 2; hf++) { bv[mi][hf] = -CUDART_INF_F; bi[mi][hf] = 0; }

    // 3-stage ring offsets (dynamic; TOT=40 not divisible by 3)
    uint32_t csOff = 0;                    // compute stage byte offset
    uint32_t pfOff = 2 * BSTAGE_B;         // prefetch stage byte offset
    const __half* pBt = bBw;               // current tile's B base (per warp)

    for (int pt = 0; pt < PTILES; pt++) {
#pragma unroll
        for (int ks = 0; ks < KSTEPS; ks++) {
            CP_WAIT(1);    // this warp's stage landed (1 group/step/thread)
            __syncwarp();  // publish lanes' cp.async bytes across the warp

            // prefetch this warp's B slice 2 steps ahead (compile-time ks)
            const int ks2 = ks + 2;
            if (ks2 < KSTEPS) {
                LOAD_BSTAGE(smb + ABOFF + pfOff, pBt + ks2 * 32);
            } else if (pt < PTILES - 1) {
                LOAD_BSTAGE(smb + ABOFF + pfOff,
                            pBt + (size_t)TP * KEXP + (ks2 - KSTEPS) * 32);
            }
            CP_COMMIT();   // exactly one group per step keeps wait-count math

            // compute: A resident (K offset ks*64B const), B from stage.
            // ks==9,kh==1 covers K[304,320) = all zero pad -> skip (bit-exact).
            const uint32_t sbB = smb + ABOFF + csOff;
#pragma unroll
            for (int kh = 0; kh < 2; kh++) {
                if (ks == KSTEPS - 1 && kh == 1) continue;
                const uint32_t ko = (uint32_t)(ks * 64 + kh * 32);
                uint32_t af[4][4], bf[4][4];
#pragma unroll
                for (int mi = 0; mi < 4; mi++) LDSM4(af[mi], aoffs[mi] + ko);
#pragma unroll
                for (int g = 0; g < 4; g++)
                    LDSM4(bf[g], sbB + boffb[g] + (uint32_t)(kh * 32));
#pragma unroll
                for (int mi = 0; mi < 4; mi++)
#pragma unroll
                    for (int pi = 0; pi < 8; pi++) {
                        const int g = pi >> 1, q = (pi & 1) * 2;
                        MMA16816(acc[mi][pi], af[mi], bf[g][q], bf[g][q + 1]);
                    }
            }

            // advance ring offsets (2 ALU each)
            csOff += BSTAGE_B; if (csOff == 3 * BSTAGE_B) csOff = 0;
            pfOff += BSTAGE_B; if (pfOff == 3 * BSTAGE_B) pfOff = 0;
        }

        // end of p-tile: fold accumulators (register-only)
        const int p0 = pchunk + pt * TP;
#pragma unroll
        for (int pi = 0; pi < 8; pi++) {
            const int pA = p0 + wp * 64 + pi * 8 + (L & 3) * 2;
            const float h0 = __ldg(h + pA), h1 = __ldg(h + pA + 1);
#pragma unroll
            for (int mi = 0; mi < 4; mi++)
#pragma unroll
                for (int hf = 0; hf < 2; hf++) {
                    float s0 = acc[mi][pi][hf * 2 + 0] + h0;
                    float s1 = acc[mi][pi][hf * 2 + 1] + h1;
                    if (s0 > bv[mi][hf]) { bv[mi][hf] = s0; bi[mi][hf] = pA; }
                    if (s1 > bv[mi][hf]) { bv[mi][hf] = s1; bi[mi][hf] = pA + 1; }
                    acc[mi][pi][hf * 2 + 0] = 0.0f;
                    acc[mi][pi][hf * 2 + 1] = 0.0f;
                }
        }
        pBt += (size_t)TP * KEXP;
    }

    // reduce: lanes sharing an n-row differ in L&3 (disjoint p); then across
    // the 4 warps (disjoint p slices, wp ascending = p ascending).
    __syncthreads();
    float* rv = reinterpret_cast<float*>(smem + REDOFF);          // [4][64]
    int*   ri = reinterpret_cast<int*>(smem + REDOFF + 1024);     // [4][64]
#pragma unroll
    for (int mi = 0; mi < 4; mi++)
#pragma unroll
        for (int hf = 0; hf < 2; hf++) {
            float v = bv[mi][hf];
            int   i = bi[mi][hf];
#pragma unroll
            for (int off = 1; off <= 2; off <<= 1) {
                float ov = __shfl_xor_sync(0xffffffffu, v, off);
                int   oi = __shfl_xor_sync(0xffffffffu, i, off);
                if (ov > v || (ov == v && oi < i)) { v = ov; i = oi; }
            }
            if ((L & 3) == 0) {
                int row = mi * 16 + (L >> 2) + hf * 8;            // 0..63
                rv[wp * 64 + row] = v;
                ri[wp * 64 + row] = i;
            }
        }
    __syncthreads();
    if (tid < NT) {
        float v = rv[tid]; int i = ri[tid];
#pragma unroll
        for (int w = 1; w < 4; w++) {
            float ov = rv[w * 64 + tid]; int oi = ri[w * 64 + tid];
            if (ov > v) { v = ov; i = oi; }
        }
        g_pv[pc * BATN + nbase + tid] = v;
        g_pi[pc * BATN + nbase + tid] = i;
    }
}

// ---------------- combine chunks + outputs + bincount ----------------
__global__ void combine_kernel(float* __restrict__ out) {
    int n = blockIdx.x * blockDim.x + threadIdx.x;
    if (n >= BATN) return;
    float v = g_pv[n]; int i = g_pi[n];
#pragma unroll
    for (int c = 1; c < PCHUNKS; c++) {
        float cv = g_pv[c * BATN + n]; int ci = g_pi[c * BATN + n];
        if (cv > v) { v = cv; i = ci; }       // chunks ascending in p
    }
    out[n]        = v;
    out[BATN + n] = (float)i;
    atomicAdd(&out[2 * BATN + i], 1.0f / (float)BATN);
}

// ---------------- launch ----------------
extern "C" void kernel_launch(void* const* d_in, const int* in_sizes, int n_in,
                              void* d_out, int out_size) {
    const float* P = (const float*)d_in[0];   // h_P [16384,100]
    const float* h = (const float*)d_in[1];   // h   [16384]
    const float* X = (const float*)d_in[2];   // volP[8192,100]
    float* out = (float*)d_out;
    (void)in_sizes; (void)n_in; (void)out_size;

    static bool attr_set = false;
    if (!attr_set) {
        cudaFuncSetAttribute(ot_mma_kernel,
                             cudaFuncAttributeMaxDynamicSharedMemorySize, SMEM_TOTAL);
        attr_set = true;
    }

    const int nchunks = (BATN + NUM_P) * 40;              // 983040
    prep_kernel<<<(nchunks + 255) / 256, 256>>>(X, P, out + 2 * BATN);
    ot_mma_kernel<<<128 * PCHUNKS, THREADS, SMEM_TOTAL>>>(h);
    combine_kernel<<<(BATN + 255) / 256, 256>>>(out);
}